// round 12
// baseline (speedup 1.0000x reference)
#include <cuda_runtime.h>
#include <cuda_bf16.h>
#include <cuda_fp16.h>
#include <cstdint>
#include <cstddef>

// Problem shape (fixed by reference): B=16, T=1024, D=256
#define BB 16
#define TT 1024
#define DD 256

#define TILE 128
#define KC   32       // K chunk staged through smem (8 chunks)
#define STRIDE 40     // bf16 units per smem row (32+8 pad): conflict-free ldsm
#define WSTR 136      // fp16 units per w-smem row (128+8 pad)

#define C_YX 61.72839506172839f   // 1/(2*0.09^2)
#define C_HW 5.555555555555555f   // 1/(2*0.3^2)

// smem layout (bytes): A 10240 | B 10240 | W 34816 | red 64
#define SM_A   0
#define SM_B   10240
#define SM_W   20480
#define SM_RED 55296
#define SMEM_TOTAL 55360

__device__ float g_pw[BB * 64];    // per-CTA partial Sum(w)
__device__ float g_pwg[BB * 64];   // per-CTA partial Sum(w*G)

__device__ __forceinline__ uint32_t smem_u32(const void* p) {
    return (uint32_t)__cvta_generic_to_shared(p);
}
__device__ __forceinline__ void mma_bf16(float c[4], const uint32_t a[4], const uint32_t b0,
                                         const uint32_t b1) {
    asm volatile(
        "mma.sync.aligned.m16n8k16.row.col.f32.bf16.bf16.f32 "
        "{%0,%1,%2,%3}, {%4,%5,%6,%7}, {%8,%9}, {%0,%1,%2,%3};"
        : "+f"(c[0]), "+f"(c[1]), "+f"(c[2]), "+f"(c[3])
        : "r"(a[0]), "r"(a[1]), "r"(a[2]), "r"(a[3]), "r"(b0), "r"(b1));
}
__device__ __forceinline__ void ldsm_x4(uint32_t r[4], uint32_t a) {
    asm volatile("ldmatrix.sync.aligned.m8n8.x4.shared.b16 {%0,%1,%2,%3}, [%4];"
        : "=r"(r[0]), "=r"(r[1]), "=r"(r[2]), "=r"(r[3]) : "r"(a));
}
__device__ __forceinline__ void ldsm_x2(uint32_t r[2], uint32_t a) {
    asm volatile("ldmatrix.sync.aligned.m8n8.x2.shared.b16 {%0,%1}, [%2];"
        : "=r"(r[0]), "=r"(r[1]) : "r"(a));
}

// ---------------------------------------------------------------------------
// Fused (no prep): one CTA per (t-tile, s-tile, b).
//  Phase 1: Gram tile via bf16 mma.sync; A/B staged per K-chunk by loading
//           z fp32 (L2-resident), converting to bf16 in registers, STS.
//  Phase 2: stream dT tile (__ldcs, read-once) -> w fp16 smem + Sum w.
//  Phase 3: combine Sum(w*G) from fragments vs smem w.
//  num = 2*Sum(w) - 2*Sum(w*G)   (z is L2-normalized -> z2 == 1).
// Partials written to unique global slots (no atomics, no init kernel).
// grid = (8,8,16), block = 256 (8 warps; 2x4 warp grid, 64x32 per warp).
// ---------------------------------------------------------------------------
__global__ __launch_bounds__(256, 2)
void fused_kernel(const float* __restrict__ z, const float4* __restrict__ dT4) {
    extern __shared__ char sm[];
    const uint32_t smb = smem_u32(sm);
    __nv_bfloat16* smA = (__nv_bfloat16*)(sm + SM_A);
    __nv_bfloat16* smB = (__nv_bfloat16*)(sm + SM_B);
    __half*        smW = (__half*)(sm + SM_W);
    float*         red = (float*)(sm + SM_RED);

    const int b  = blockIdx.z;
    const int t0 = blockIdx.y * TILE;
    const int s0 = blockIdx.x * TILE;

    const int tid  = threadIdx.x;
    const int warp = tid >> 5;
    const int lane = tid & 31;
    const int wm   = warp & 1;   // row half (64 rows)
    const int wn   = warp >> 1;  // col quarter (32 cols)
    const int g    = lane >> 2;
    const int tg   = lane & 3;

    // ---- staging coords: thread covers row tid>>1, 16-col half (tid&1) ------
    const int srow = tid >> 1;
    const int shalf = (tid & 1);                  // 0 or 1 (cols half*16..+16)
    const float4* zA4 = (const float4*)(z + ((size_t)b * TT + t0 + srow) * DD) + shalf * 4;
    const float4* zB4 = (const float4*)(z + ((size_t)b * TT + s0 + srow) * DD) + shalf * 4;
    __nv_bfloat16* stA = smA + srow * STRIDE + shalf * 16;
    __nv_bfloat16* stB = smB + srow * STRIDE + shalf * 16;

    // ---- ldsm byte offsets (proven R9 pattern, STRIDE 40) --------------------
    const uint32_t smA_u = smb + SM_A;
    const uint32_t smB_u = smb + SM_B;
    uint32_t offA[4], offB[4];
    {
        const int rowA = lane & 15;
        const int colA = (lane >> 4) << 3;
#pragma unroll
        for (int mi = 0; mi < 4; mi++)
            offA[mi] = ((wm * 64 + mi * 16 + rowA) * STRIDE + colA) * 2;
        const int rowB = lane & 7;
        const int colB = ((lane >> 3) & 1) << 3;
#pragma unroll
        for (int ni = 0; ni < 4; ni++)
            offB[ni] = ((wn * 32 + ni * 8 + rowB) * STRIDE + colB) * 2;
    }

    float acc[16][4];
#pragma unroll
    for (int i = 0; i < 16; i++)
#pragma unroll
        for (int j = 0; j < 4; j++) acc[i][j] = 0.0f;

    // ================= Phase 1: Gram tile =====================================
#pragma unroll
    for (int kci = 0; kci < DD / KC; kci++) {
        const int f4o = kci * 8;   // f4 index offset for this chunk (32 floats)

        // front-batch 8 independent LDG.128 (one L2 round trip)
        float4 va[4], vb[4];
#pragma unroll
        for (int i = 0; i < 4; i++) va[i] = __ldg(zA4 + f4o + i);
#pragma unroll
        for (int i = 0; i < 4; i++) vb[i] = __ldg(zB4 + f4o + i);

        // convert to bf16 and store (2 x 16B per tile)
        uint32_t pa[8], pb[8];
#pragma unroll
        for (int i = 0; i < 4; i++) {
            __nv_bfloat162 lo = __floats2bfloat162_rn(va[i].x, va[i].y);
            __nv_bfloat162 hi = __floats2bfloat162_rn(va[i].z, va[i].w);
            pa[i * 2]     = *(uint32_t*)&lo;
            pa[i * 2 + 1] = *(uint32_t*)&hi;
            __nv_bfloat162 lo2 = __floats2bfloat162_rn(vb[i].x, vb[i].y);
            __nv_bfloat162 hi2 = __floats2bfloat162_rn(vb[i].z, vb[i].w);
            pb[i * 2]     = *(uint32_t*)&lo2;
            pb[i * 2 + 1] = *(uint32_t*)&hi2;
        }
        *(uint4*)(stA)     = make_uint4(pa[0], pa[1], pa[2], pa[3]);
        *(uint4*)(stA + 8) = make_uint4(pa[4], pa[5], pa[6], pa[7]);
        *(uint4*)(stB)     = make_uint4(pb[0], pb[1], pb[2], pb[3]);
        *(uint4*)(stB + 8) = make_uint4(pb[4], pb[5], pb[6], pb[7]);
        __syncthreads();

#pragma unroll
        for (int k0 = 0; k0 < KC; k0 += 16) {
            uint32_t af[4][4], bf[4][2];
#pragma unroll
            for (int mi = 0; mi < 4; mi++) ldsm_x4(af[mi], smA_u + offA[mi] + k0 * 2);
#pragma unroll
            for (int ni = 0; ni < 4; ni++) ldsm_x2(bf[ni], smB_u + offB[ni] + k0 * 2);
#pragma unroll
            for (int mi = 0; mi < 4; mi++)
#pragma unroll
                for (int ni = 0; ni < 4; ni++)
                    mma_bf16(acc[mi * 4 + ni], af[mi], bf[ni][0], bf[ni][1]);
        }
        __syncthreads();
    }

    // ================= Phase 2: stream dT tile ================================
    const size_t dbase = (size_t)b * TT * TT + (size_t)t0 * TT + s0;
    float sum_w = 0.0f;
#pragma unroll 4
    for (int r = 0; r < 16; r++) {
        const int row = warp * 16 + r;
        const float4* p = dT4 + dbase + (size_t)row * TT;
        __half* wrow = smW + row * WSTR;
#pragma unroll
        for (int it = 0; it < 4; it++) {
            float4 d = __ldcs(p + it * 32 + lane);     // read-once: evict-first
            float e = (d.x * d.x + d.y * d.y) * C_YX
                    + (d.z * d.z + d.w * d.w) * C_HW;
            float w = __expf(-e);
            sum_w += w;
            wrow[it * 32 + lane] = __float2half_rn(w);
        }
    }
    __syncthreads();

    // ================= Phase 3: combine Sum(w*G) ==============================
    float sum_wg = 0.0f;
#pragma unroll
    for (int mi = 0; mi < 4; mi++) {
        const int tt = wm * 64 + mi * 16 + g;
#pragma unroll
        for (int ni = 0; ni < 4; ni++) {
            const int ss = wn * 32 + ni * 8 + 2 * tg;
            const float* a = acc[mi * 4 + ni];
            float2 f0 = __half22float2(*(const __half2*)&smW[tt * WSTR + ss]);
            float2 f1 = __half22float2(*(const __half2*)&smW[(tt + 8) * WSTR + ss]);
            sum_wg += f0.x * a[0] + f0.y * a[1] + f1.x * a[2] + f1.y * a[3];
        }
    }

    // ---- reduce + write per-CTA partials (unique slot, no atomics) ----------
#pragma unroll
    for (int o = 16; o > 0; o >>= 1) {
        sum_w  += __shfl_down_sync(0xFFFFFFFFu, sum_w,  o);
        sum_wg += __shfl_down_sync(0xFFFFFFFFu, sum_wg, o);
    }
    if (lane == 0) { red[warp] = sum_w; red[8 + warp] = sum_wg; }
    __syncthreads();
    if (tid == 0) {
        float W = 0.0f, WG = 0.0f;
#pragma unroll
        for (int i = 0; i < 8; i++) { W += red[i]; WG += red[8 + i]; }
        const int slot = b * 64 + blockIdx.y * 8 + blockIdx.x;
        g_pw[slot]  = W;
        g_pwg[slot] = WG;
    }
}

// ---------------------------------------------------------------------------
// Finalize: warp i reduces batch i's 64 partials; mean of num/den over batches.
// num_b = 2*(W_b - WG_b), den_b = max(W_b, 1e-6).
// ---------------------------------------------------------------------------
__global__ void final_kernel(float* __restrict__ out) {
    __shared__ float sred[16];
    const int warp = threadIdx.x >> 5;
    const int lane = threadIdx.x & 31;
    float W  = g_pw[warp * 64 + lane]  + g_pw[warp * 64 + 32 + lane];
    float WG = g_pwg[warp * 64 + lane] + g_pwg[warp * 64 + 32 + lane];
#pragma unroll
    for (int o = 16; o > 0; o >>= 1) {
        W  += __shfl_down_sync(0xFFFFFFFFu, W,  o);
        WG += __shfl_down_sync(0xFFFFFFFFu, WG, o);
    }
    if (lane == 0) sred[warp] = 2.0f * (W - WG) / fmaxf(W, 1e-6f);
    __syncthreads();
    if (threadIdx.x == 0) {
        float s = 0.0f;
#pragma unroll
        for (int i = 0; i < 16; i++) s += sred[i];
        out[0] = s * (1.0f / BB);
    }
}

extern "C" void kernel_launch(void* const* d_in, const int* in_sizes, int n_in,
                              void* d_out, int out_size) {
    const float* z  = (const float*)d_in[0];
    const float* dT = (const float*)d_in[1];
    // Defensive: z has B*T*D = 4.19M elems, gt_dT has B*T*T*4 = 67.1M.
    if (n_in >= 2 && in_sizes[0] > in_sizes[1]) {
        const float* tmp = z; z = dT; dT = tmp;
    }
    (void)out_size;

    cudaFuncSetAttribute(fused_kernel,
                         cudaFuncAttributeMaxDynamicSharedMemorySize, SMEM_TOTAL);

    dim3 grid(TT / TILE, TT / TILE, BB);
    fused_kernel<<<grid, 256, SMEM_TOTAL>>>(z, (const float4*)dT);

    final_kernel<<<1, 512>>>((float*)d_out);
}

// round 13
// speedup vs baseline: 1.5214x; 1.5214x over previous
#include <cuda_runtime.h>
#include <cuda_bf16.h>
#include <cuda_fp16.h>
#include <cstdint>
#include <cstddef>

// Problem shape (fixed by reference): B=16, T=1024, D=256
#define BB 16
#define TT 1024
#define DD 256

#define TILE 128
#define KC   32       // K chunk staged through smem (8 chunks)
#define STRIDE 40     // bf16 units per smem row (32+8 pad): conflict-free ldsm
#define WSTR 136      // fp16 units per w-smem row (128+8 pad)

#define C_YX 61.72839506172839f   // 1/(2*0.09^2)
#define C_HW 5.555555555555555f   // 1/(2*0.3^2)

// smem layout (bytes): A 2x10240 | B 2x10240 | W 34816 | red 64  (W separate:
// phases can run in either order, so W must not overlay the GEMM buffers)
#define SM_B_OFF 20480
#define SM_W_OFF 40960
#define SM_RED   75776
#define SMEM_TOTAL 75840

__device__ float g_num[BB];
__device__ float g_den[BB];
__device__ __nv_bfloat16 g_zb[BB * TT * DD];   // bf16 copy of z (8.4 MB scratch)

__device__ __forceinline__ uint32_t smem_u32(const void* p) {
    return (uint32_t)__cvta_generic_to_shared(p);
}
__device__ __forceinline__ void cp16(uint32_t dst, const void* src) {
    asm volatile("cp.async.cg.shared.global [%0], [%1], 16;\n" :: "r"(dst), "l"(src));
}
__device__ __forceinline__ void mma_bf16(float c[4], const uint32_t a[4], const uint32_t b0,
                                         const uint32_t b1) {
    asm volatile(
        "mma.sync.aligned.m16n8k16.row.col.f32.bf16.bf16.f32 "
        "{%0,%1,%2,%3}, {%4,%5,%6,%7}, {%8,%9}, {%0,%1,%2,%3};"
        : "+f"(c[0]), "+f"(c[1]), "+f"(c[2]), "+f"(c[3])
        : "r"(a[0]), "r"(a[1]), "r"(a[2]), "r"(a[3]), "r"(b0), "r"(b1));
}
__device__ __forceinline__ void ldsm_x4(uint32_t r[4], uint32_t a) {
    asm volatile("ldmatrix.sync.aligned.m8n8.x4.shared.b16 {%0,%1,%2,%3}, [%4];"
        : "=r"(r[0]), "=r"(r[1]), "=r"(r[2]), "=r"(r[3]) : "r"(a));
}
__device__ __forceinline__ void ldsm_x2(uint32_t r[2], uint32_t a) {
    asm volatile("ldmatrix.sync.aligned.m8n8.x2.shared.b16 {%0,%1}, [%2];"
        : "=r"(r[0]), "=r"(r[1]) : "r"(a));
}

// ---------------------------------------------------------------------------
// Prep: z (fp32) -> g_zb (bf16); zero accumulators. 1024x256, 4 f4/thread.
// ---------------------------------------------------------------------------
__global__ void prep_kernel(const float4* __restrict__ z4) {
    if (blockIdx.x == 0 && threadIdx.x < BB) {
        g_num[threadIdx.x] = 0.0f;
        g_den[threadIdx.x] = 0.0f;
    }
    int base = blockIdx.x * 1024 + threadIdx.x;
#pragma unroll
    for (int i = 0; i < 4; i++) {
        int idx = base + i * 256;
        float4 v = z4[idx];
        __nv_bfloat162 lo = __floats2bfloat162_rn(v.x, v.y);
        __nv_bfloat162 hi = __floats2bfloat162_rn(v.z, v.w);
        uint2 pk;
        pk.x = *(uint32_t*)&lo;
        pk.y = *(uint32_t*)&hi;
        *(uint2*)(g_zb + (size_t)idx * 4) = pk;
    }
}

// ---------------------------------------------------------------------------
// Fused with per-CTA phase swap: even blockIdx.x CTAs run GEMM -> stream,
// odd CTAs run stream -> GEMM. Phases are independent (GEMM uses z only,
// stream uses dT only), so alternating their order across CTAs keeps DRAM
// busy while other CTAs compute, instead of chip-wide phase alignment.
//  GEMM:   128x128 Gram tile via bf16 mma.sync, cp.async double-buffered.
//  stream: dT tile -> w = exp(-e) (fp16 smem) + Sum w.
//  combine: Sum(w*G) fragments vs smem w.  num = 2*Sum(w) - 2*Sum(w*G).
// grid = (8,8,16), block = 256 (8 warps; 2x4 warp grid, 64x32 per warp).
// ---------------------------------------------------------------------------
__global__ __launch_bounds__(256, 2)
void fused_kernel(const float4* __restrict__ dT4) {
    extern __shared__ char sm[];
    const uint32_t smb = smem_u32(sm);
    __nv_bfloat16* smA = (__nv_bfloat16*)(sm);
    __nv_bfloat16* smB = (__nv_bfloat16*)(sm + SM_B_OFF);
    __half*        smW = (__half*)(sm + SM_W_OFF);
    float*         red = (float*)(sm + SM_RED);

    const int b  = blockIdx.z;
    const int t0 = blockIdx.y * TILE;
    const int s0 = blockIdx.x * TILE;

    const int tid  = threadIdx.x;
    const int warp = tid >> 5;
    const int lane = tid & 31;
    const int wm   = warp & 1;   // row half (64 rows)
    const int wn   = warp >> 1;  // col quarter (32 cols)
    const int g    = lane >> 2;
    const int tg   = lane & 3;

    float acc[16][4];
#pragma unroll
    for (int i = 0; i < 16; i++)
#pragma unroll
        for (int j = 0; j < 4; j++) acc[i][j] = 0.0f;
    float sum_w = 0.0f;

    // ---------------- GEMM phase (R9-proven internals) ----------------------
    auto gemm_phase = [&]() {
        const __nv_bfloat16* zbA = g_zb + (size_t)b * TT * DD + (size_t)t0 * DD;
        const __nv_bfloat16* zbB = g_zb + (size_t)b * TT * DD + (size_t)s0 * DD;

        const int sr0 = tid >> 2, sc0 = tid & 3;
        const int sr1 = (tid + 256) >> 2, sc1 = (tid + 256) & 3;

        uint32_t offA[4], offB[4];
        {
            const int rowA = lane & 15;
            const int colA = (lane >> 4) << 3;
#pragma unroll
            for (int mi = 0; mi < 4; mi++)
                offA[mi] = ((wm * 64 + mi * 16 + rowA) * STRIDE + colA) * 2;
            const int rowB = lane & 7;
            const int colB = ((lane >> 3) & 1) << 3;
#pragma unroll
            for (int ni = 0; ni < 4; ni++)
                offB[ni] = ((wn * 32 + ni * 8 + rowB) * STRIDE + colB) * 2;
        }

        cp16(smb + (sr0 * STRIDE + sc0 * 8) * 2,            zbA + (size_t)sr0 * DD + sc0 * 8);
        cp16(smb + SM_B_OFF + (sr0 * STRIDE + sc0 * 8) * 2, zbB + (size_t)sr0 * DD + sc0 * 8);
        cp16(smb + (sr1 * STRIDE + sc1 * 8) * 2,            zbA + (size_t)sr1 * DD + sc1 * 8);
        cp16(smb + SM_B_OFF + (sr1 * STRIDE + sc1 * 8) * 2, zbB + (size_t)sr1 * DD + sc1 * 8);
        asm volatile("cp.async.commit_group;\n" ::);

#pragma unroll
        for (int kci = 0; kci < DD / KC; kci++) {
            const int cb = kci & 1;
            if (kci < DD / KC - 1) {
                const int kn = (kci + 1) * KC;
                const int nb = (kci + 1) & 1;
                const uint32_t bA = smb + nb * (TILE * STRIDE * 2);
                const uint32_t bB = smb + SM_B_OFF + nb * (TILE * STRIDE * 2);
                cp16(bA + (sr0 * STRIDE + sc0 * 8) * 2, zbA + (size_t)sr0 * DD + kn + sc0 * 8);
                cp16(bB + (sr0 * STRIDE + sc0 * 8) * 2, zbB + (size_t)sr0 * DD + kn + sc0 * 8);
                cp16(bA + (sr1 * STRIDE + sc1 * 8) * 2, zbA + (size_t)sr1 * DD + kn + sc1 * 8);
                cp16(bB + (sr1 * STRIDE + sc1 * 8) * 2, zbB + (size_t)sr1 * DD + kn + sc1 * 8);
                asm volatile("cp.async.commit_group;\n" ::);
                asm volatile("cp.async.wait_group 1;\n" ::);
            } else {
                asm volatile("cp.async.wait_group 0;\n" ::);
            }
            __syncthreads();

            const uint32_t bufA = smb + cb * (TILE * STRIDE * 2);
            const uint32_t bufB = smb + SM_B_OFF + cb * (TILE * STRIDE * 2);
#pragma unroll
            for (int k0 = 0; k0 < KC; k0 += 16) {
                uint32_t af[4][4], bf[4][2];
#pragma unroll
                for (int mi = 0; mi < 4; mi++) ldsm_x4(af[mi], bufA + offA[mi] + k0 * 2);
#pragma unroll
                for (int ni = 0; ni < 4; ni++) ldsm_x2(bf[ni], bufB + offB[ni] + k0 * 2);
#pragma unroll
                for (int mi = 0; mi < 4; mi++)
#pragma unroll
                    for (int ni = 0; ni < 4; ni++)
                        mma_bf16(acc[mi * 4 + ni], af[mi], bf[ni][0], bf[ni][1]);
            }
            __syncthreads();
        }
    };

    // ---------------- stream phase (R7-proven internals) --------------------
    auto stream_phase = [&]() {
        const size_t dbase = (size_t)b * TT * TT + (size_t)t0 * TT + s0;
#pragma unroll 4
        for (int r = 0; r < 16; r++) {
            const int row = warp * 16 + r;
            const float4* p = dT4 + dbase + (size_t)row * TT;
            __half* wrow = smW + row * WSTR;
#pragma unroll
            for (int it = 0; it < 4; it++) {
                float4 d = __ldg(p + it * 32 + lane);
                float e = (d.x * d.x + d.y * d.y) * C_YX
                        + (d.z * d.z + d.w * d.w) * C_HW;
                float w = __expf(-e);
                sum_w += w;
                wrow[it * 32 + lane] = __float2half_rn(w);
            }
        }
    };

    // ---- per-CTA phase order swap (desynchronizes DRAM demand) -------------
    if (blockIdx.x & 1) { stream_phase(); gemm_phase(); }
    else                { gemm_phase();  stream_phase(); }
    __syncthreads();   // w tile complete + all acc done

    // ---------------- combine: Sum(w*G) --------------------------------------
    float sum_wg = 0.0f;
#pragma unroll
    for (int mi = 0; mi < 4; mi++) {
        const int tt = wm * 64 + mi * 16 + g;
#pragma unroll
        for (int ni = 0; ni < 4; ni++) {
            const int ss = wn * 32 + ni * 8 + 2 * tg;
            const float* a = acc[mi * 4 + ni];
            float2 f0 = __half22float2(*(const __half2*)&smW[tt * WSTR + ss]);
            float2 f1 = __half22float2(*(const __half2*)&smW[(tt + 8) * WSTR + ss]);
            sum_wg += f0.x * a[0] + f0.y * a[1] + f1.x * a[2] + f1.y * a[3];
        }
    }

    // ---------------- reduce + accumulate ------------------------------------
#pragma unroll
    for (int o = 16; o > 0; o >>= 1) {
        sum_w  += __shfl_down_sync(0xFFFFFFFFu, sum_w,  o);
        sum_wg += __shfl_down_sync(0xFFFFFFFFu, sum_wg, o);
    }
    if (lane == 0) { red[warp] = sum_w; red[8 + warp] = sum_wg; }
    __syncthreads();
    if (tid == 0) {
        float W = 0.0f, WG = 0.0f;
#pragma unroll
        for (int i = 0; i < 8; i++) { W += red[i]; WG += red[8 + i]; }
        atomicAdd(&g_den[b], W);
        atomicAdd(&g_num[b], 2.0f * (W - WG));
    }
}

// ---------------------------------------------------------------------------
// Finalize: mean over batches of num / max(den, 1e-6)
// ---------------------------------------------------------------------------
__global__ void final_kernel(float* __restrict__ out) {
    int lane = threadIdx.x;
    float r = 0.0f;
    if (lane < BB) r = g_num[lane] / fmaxf(g_den[lane], 1e-6f);
#pragma unroll
    for (int o = 16; o > 0; o >>= 1) r += __shfl_down_sync(0xFFFFFFFFu, r, o);
    if (lane == 0) out[0] = r * (1.0f / BB);
}

extern "C" void kernel_launch(void* const* d_in, const int* in_sizes, int n_in,
                              void* d_out, int out_size) {
    const float* z  = (const float*)d_in[0];
    const float* dT = (const float*)d_in[1];
    // Defensive: z has B*T*D = 4.19M elems, gt_dT has B*T*T*4 = 67.1M.
    if (n_in >= 2 && in_sizes[0] > in_sizes[1]) {
        const float* tmp = z; z = dT; dT = tmp;
    }
    (void)out_size;

    cudaFuncSetAttribute(fused_kernel,
                         cudaFuncAttributeMaxDynamicSharedMemorySize, SMEM_TOTAL);

    prep_kernel<<<1024, 256>>>((const float4*)z);

    dim3 grid(TT / TILE, TT / TILE, BB);
    fused_kernel<<<grid, 256, SMEM_TOTAL>>>((const float4*)dT);

    final_kernel<<<1, 32>>>((float*)d_out);
}

// round 15
// speedup vs baseline: 1.6679x; 1.0963x over previous
#include <cuda_runtime.h>
#include <cuda_bf16.h>
#include <cstdint>
#include <cstddef>

// Problem shape (fixed by reference): B=16, T=1024, D=256
#define BB 16
#define TT 1024
#define DD 256

#define TILE 128      // (t,s) tile per CTA
#define KC   32       // K chunk staged through smem (8 chunks)
#define STRIDE 40     // bf16 units per smem row (32+8 pad): conflict-free, 16B-aligned rows

#define C_YX 61.72839506172839f   // 1/(2*0.09^2)
#define C_HW 5.555555555555555f   // 1/(2*0.3^2)

__device__ float g_num[BB];
__device__ float g_den[BB];
__device__ __nv_bfloat16 g_zb[BB * TT * DD];   // bf16 copy of z (8.4 MB scratch)

__device__ __forceinline__ void cp16(void* dst, const void* src) {
    uint32_t d = (uint32_t)__cvta_generic_to_shared(dst);
    asm volatile("cp.async.cg.shared.global [%0], [%1], 16;\n" :: "r"(d), "l"(src));
}
__device__ __forceinline__ void prefetch_l2(const void* p) {
    asm volatile("prefetch.global.L2 [%0];" :: "l"(p));
}
__device__ __forceinline__ void mma_bf16(float c[4], const uint32_t a[4], const uint32_t b[2]) {
    asm volatile(
        "mma.sync.aligned.m16n8k16.row.col.f32.bf16.bf16.f32 "
        "{%0,%1,%2,%3}, {%4,%5,%6,%7}, {%8,%9}, {%0,%1,%2,%3};"
        : "+f"(c[0]), "+f"(c[1]), "+f"(c[2]), "+f"(c[3])
        : "r"(a[0]), "r"(a[1]), "r"(a[2]), "r"(a[3]), "r"(b[0]), "r"(b[1]));
}

// ---------------------------------------------------------------------------
// Prep: z (fp32) -> g_zb (bf16); zero accumulators. 1024x256, 4 f4/thread.
// ---------------------------------------------------------------------------
__global__ void prep_kernel(const float4* __restrict__ z4) {
    if (blockIdx.x == 0 && threadIdx.x < BB) {
        g_num[threadIdx.x] = 0.0f;
        g_den[threadIdx.x] = 0.0f;
    }
    int base = blockIdx.x * 1024 + threadIdx.x;
#pragma unroll
    for (int i = 0; i < 4; i++) {
        int idx = base + i * 256;
        float4 v = z4[idx];
        __nv_bfloat162 lo = __floats2bfloat162_rn(v.x, v.y);
        __nv_bfloat162 hi = __floats2bfloat162_rn(v.z, v.w);
        uint2 pk;
        pk.x = *(uint32_t*)&lo;
        pk.y = *(uint32_t*)&hi;
        *(uint2*)(g_zb + (size_t)idx * 4) = pk;
    }
}

// ---------------------------------------------------------------------------
// Fused (R7 champion skeleton + L2 prefetch smoothing):
//  Phase 1: 128x128 Gram tile via bf16 mma.sync, cp.async double-buffered;
//           each K-chunk iteration additionally issues 1 prefetch.global.L2
//           per thread on this CTA's dT tile (2048 x 128B lines over 8 iters)
//           so DRAM stays busy during the GEMM window.
//  Phase 2: epilogue streams the dT tile (now L2-hot), w = exp(-e),
//           accumulates Sum w and Sum w*(2-2G)   (z L2-normalized -> z2=1).
// grid = (8,8,16), block = 256 (8 warps; 2x4 warp grid, 64x32 per warp).
// ---------------------------------------------------------------------------
__global__ __launch_bounds__(256, 2)
void fused_kernel(const float4* __restrict__ dT4) {
    __shared__ __nv_bfloat16 smA[2][TILE * STRIDE];
    __shared__ __nv_bfloat16 smB[2][TILE * STRIDE];
    __shared__ float red0[8], red1[8];

    const int b  = blockIdx.z;
    const int t0 = blockIdx.y * TILE;
    const int s0 = blockIdx.x * TILE;

    const __nv_bfloat16* zbA = g_zb + (size_t)b * TT * DD + (size_t)t0 * DD;
    const __nv_bfloat16* zbB = g_zb + (size_t)b * TT * DD + (size_t)s0 * DD;

    const int tid  = threadIdx.x;
    const int warp = tid >> 5;
    const int lane = tid & 31;
    const int wm   = warp & 1;   // row half (64 rows)
    const int wn   = warp >> 1;  // col quarter (32 cols)
    const int g    = lane >> 2;
    const int tg   = lane & 3;

    const size_t dbase = (size_t)b * TT * TT + (size_t)t0 * TT + s0;
    const char* dT_tile = (const char*)(dT4 + dbase);

    // staging coords (R7-proven): 1024 16B-units per 128x32 bf16 tile,
    // 2 units per thread per tile: sr = row, sc = 16B unit within 32-col row
    const int sr0 = tid >> 2, sc0 = tid & 3;
    const int sr1 = (tid + 256) >> 2, sc1 = (tid + 256) & 3;

    float acc[16][4];
#pragma unroll
    for (int i = 0; i < 16; i++)
#pragma unroll
        for (int j = 0; j < 4; j++) acc[i][j] = 0.0f;

    // ---- prologue: stage chunk 0 into buffer 0 ----
    cp16(&smA[0][sr0 * STRIDE + sc0 * 8], zbA + (size_t)sr0 * DD + sc0 * 8);
    cp16(&smB[0][sr0 * STRIDE + sc0 * 8], zbB + (size_t)sr0 * DD + sc0 * 8);
    cp16(&smA[0][sr1 * STRIDE + sc1 * 8], zbA + (size_t)sr1 * DD + sc1 * 8);
    cp16(&smB[0][sr1 * STRIDE + sc1 * 8], zbB + (size_t)sr1 * DD + sc1 * 8);
    asm volatile("cp.async.commit_group;\n" ::);

#pragma unroll
    for (int kci = 0; kci < DD / KC; kci++) {
        // prefetch this CTA's dT tile into L2 while tensor cores work:
        // line L = kci*256 + tid ; row = L>>4 (0..127), 128B col chunk = L&15
        {
            const int L = kci * 256 + tid;
            prefetch_l2(dT_tile + (size_t)(L >> 4) * (TT * 16) + (size_t)(L & 15) * 128);
        }

        if (kci < DD / KC - 1) {
            const int kn = (kci + 1) * KC;
            const int nb = (kci + 1) & 1;
            cp16(&smA[nb][sr0 * STRIDE + sc0 * 8], zbA + (size_t)sr0 * DD + kn + sc0 * 8);
            cp16(&smB[nb][sr0 * STRIDE + sc0 * 8], zbB + (size_t)sr0 * DD + kn + sc0 * 8);
            cp16(&smA[nb][sr1 * STRIDE + sc1 * 8], zbA + (size_t)sr1 * DD + kn + sc1 * 8);
            cp16(&smB[nb][sr1 * STRIDE + sc1 * 8], zbB + (size_t)sr1 * DD + kn + sc1 * 8);
            asm volatile("cp.async.commit_group;\n" ::);
            asm volatile("cp.async.wait_group 1;\n" ::);
        } else {
            asm volatile("cp.async.wait_group 0;\n" ::);
        }
        __syncthreads();

        const __nv_bfloat16* A = smA[kci & 1];
        const __nv_bfloat16* B = smB[kci & 1];
#pragma unroll
        for (int k0 = 0; k0 < KC; k0 += 16) {
            uint32_t af[4][4], bf[4][2];
            const int ak = k0 + 2 * tg;
#pragma unroll
            for (int mi = 0; mi < 4; mi++) {
                const __nv_bfloat16* p = &A[(wm * 64 + mi * 16 + g) * STRIDE + ak];
                af[mi][0] = *(const uint32_t*)(p);
                af[mi][1] = *(const uint32_t*)(p + 8 * STRIDE);
                af[mi][2] = *(const uint32_t*)(p + 8);
                af[mi][3] = *(const uint32_t*)(p + 8 * STRIDE + 8);
            }
#pragma unroll
            for (int ni = 0; ni < 4; ni++) {
                const __nv_bfloat16* p = &B[(wn * 32 + ni * 8 + g) * STRIDE + ak];
                bf[ni][0] = *(const uint32_t*)(p);
                bf[ni][1] = *(const uint32_t*)(p + 8);
            }
#pragma unroll
            for (int mi = 0; mi < 4; mi++)
#pragma unroll
                for (int ni = 0; ni < 4; ni++)
                    mma_bf16(acc[mi * 4 + ni], af[mi], bf[ni]);
        }
        __syncthreads();  // all warps done reading this buffer before restage
    }

    // ---- Epilogue: stream dT tile (L2-hot), accumulate -----------------------
    float sum_w = 0.0f, sum_num = 0.0f;
#pragma unroll
    for (int mi = 0; mi < 4; mi++) {
#pragma unroll
        for (int ni = 0; ni < 4; ni++) {
#pragma unroll
            for (int j = 0; j < 4; j++) {
                int tt = wm * 64 + mi * 16 + g + ((j >> 1) ? 8 : 0);
                int ss = wn * 32 + ni * 8 + 2 * tg + (j & 1);
                float4 d4 = __ldg(&dT4[dbase + (size_t)tt * TT + ss]);
                float e = (d4.x * d4.x + d4.y * d4.y) * C_YX
                        + (d4.z * d4.z + d4.w * d4.w) * C_HW;
                float w = __expf(-e);
                float G = acc[mi * 4 + ni][j];
                sum_w   += w;
                sum_num += w * (2.0f - 2.0f * G);   // z2_t = z2_s = 1
            }
        }
    }

#pragma unroll
    for (int o = 16; o > 0; o >>= 1) {
        sum_w   += __shfl_down_sync(0xFFFFFFFFu, sum_w,   o);
        sum_num += __shfl_down_sync(0xFFFFFFFFu, sum_num, o);
    }
    if (lane == 0) { red0[warp] = sum_w; red1[warp] = sum_num; }
    __syncthreads();
    if (tid == 0) {
        float W = 0.0f, NUM = 0.0f;
#pragma unroll
        for (int i = 0; i < 8; i++) { W += red0[i]; NUM += red1[i]; }
        atomicAdd(&g_den[b], W);
        atomicAdd(&g_num[b], NUM);
    }
}

// ---------------------------------------------------------------------------
// Finalize: mean over batches of num / max(den, 1e-6)
// ---------------------------------------------------------------------------
__global__ void final_kernel(float* __restrict__ out) {
    int lane = threadIdx.x;
    float r = 0.0f;
    if (lane < BB) r = g_num[lane] / fmaxf(g_den[lane], 1e-6f);
#pragma unroll
    for (int o = 16; o > 0; o >>= 1) r += __shfl_down_sync(0xFFFFFFFFu, r, o);
    if (lane == 0) out[0] = r * (1.0f / BB);
}

extern "C" void kernel_launch(void* const* d_in, const int* in_sizes, int n_in,
                              void* d_out, int out_size) {
    const float* z  = (const float*)d_in[0];
    const float* dT = (const float*)d_in[1];
    // Defensive: z has B*T*D = 4.19M elems, gt_dT has B*T*T*4 = 67.1M.
    if (n_in >= 2 && in_sizes[0] > in_sizes[1]) {
        const float* tmp = z; z = dT; dT = tmp;
    }
    (void)out_size;

    prep_kernel<<<1024, 256>>>((const float4*)z);

    dim3 grid(TT / TILE, TT / TILE, BB);
    fused_kernel<<<grid, 256>>>((const float4*)dT);

    final_kernel<<<1, 32>>>((float*)d_out);
}